// round 16
// baseline (speedup 1.0000x reference)
#include <cuda_runtime.h>
#include <cuda_bf16.h>
#include <cstdint>

#define TOTPTS 16384
#define NPTS   4096
#define KNN    16

// ---- knn v8 config ----
#define QPB  16                  // queries per block
#define SUBS 16                  // sub-threads per query
#define TILE 256
#define NTILE (NPTS / TILE)      // 16
#define BCAP 128                 // per-query (d2,idx) buffer; overflow -> exact fallback

// ---- edge_mlp smem: weights only ----
#define WBYTES  50176            // 64*392*2
#define MAIN_SMEM_BYTES 100352   // hi + lo

// Scratch (allocation-free rule: device globals)
__device__ __align__(16) float g_L[TOTPTS * 256];   // [P | R1 | R2 | R3] per point
__device__ __align__(16) float g_Q[TOTPTS * 64];    // Q per point
__device__ int g_idx[TOTPTS * KNN];
__device__ __align__(16) unsigned char g_Wpk[100352]; // packed bf16 hi(50176)+lo(50176)

// ===================== helpers =====================
__device__ __forceinline__ uint32_t smem_to_u32(const void* p) {
    uint32_t a;
    asm("{ .reg .u64 t; cvta.to.shared.u64 t, %1; cvt.u32.u64 %0, t; }" : "=r"(a) : "l"(p));
    return a;
}
#define LDSM4(r0, r1, r2, r3, addr) \
    asm volatile("ldmatrix.sync.aligned.m8n8.x4.shared.b16 {%0,%1,%2,%3}, [%4];" \
        : "=r"(r0), "=r"(r1), "=r"(r2), "=r"(r3) : "r"(addr))
#define MMA16816(c, a0, a1, a2, a3, b0, b1) \
    asm volatile("mma.sync.aligned.m16n8k16.row.col.f32.bf16.bf16.f32 " \
        "{%0,%1,%2,%3}, {%4,%5,%6,%7}, {%8,%9}, {%0,%1,%2,%3};" \
        : "+f"((c)[0]), "+f"((c)[1]), "+f"((c)[2]), "+f"((c)[3]) \
        : "r"(a0), "r"(a1), "r"(a2), "r"(a3), "r"(b0), "r"(b1))

__device__ __forceinline__ void hilo2(float a, float b, uint32_t& h, uint32_t& l) {
    __nv_bfloat16 ha = __float2bfloat16(a), hb = __float2bfloat16(b);
    float ra = a - __bfloat162float(ha), rb = b - __bfloat162float(hb);
    __nv_bfloat162 H; H.x = ha; H.y = hb;
    __nv_bfloat162 L; L.x = __float2bfloat16(ra); L.y = __float2bfloat16(rb);
    h = *(uint32_t*)&H; l = *(uint32_t*)&L;
}

// ---------------------------------------------------------------------------
// KNN v8: deferred refine + double-buffered tiles.
// Phase A (full scan): per-(query,sub) min over its 256-candidate stripe ->
//   tau0 = max of the 16 distinct sub-minima >= d16 (provable).
// Phase B: filter d2 <= tau0 (so every true top-16 member passes) -> push
//   (d2, global idx) into a per-query smem buffer. d2 is computed with the
//   exact fmaf chain used in every passing round.
// Final: one replace-max top-16 drain per query over ~30 buffered pairs.
//   n > BCAP (astronomically rare) -> exact full scan fallback.
// One __syncthreads per tile (double-buffered sp); no per-tile serial refine.
// ---------------------------------------------------------------------------
__global__ __launch_bounds__(256) void knn_kernel(const float* __restrict__ pos) {
    __shared__ float4 sp[2][TILE];        // 8 KB
    __shared__ float  bufD[QPB][BCAP];    // 8 KB
    __shared__ int    bufI[QPB][BCAP];    // 8 KB
    __shared__ float  seedD[QPB * SUBS];  // 1 KB
    __shared__ float  stau[QPB];
    __shared__ int    scnt[QPB];

    int t   = threadIdx.x;
    int ql  = t >> 4;
    int sub = t & 15;
    int qg  = blockIdx.x * QPB + ql;
    int b   = qg >> 12;
    int q   = qg & 4095;
    const float* pb = pos + b * NPTS * 3;

    if (t < QPB) scnt[t] = 0;

    float qx = __ldg(pb + q * 3 + 0);
    float qy = __ldg(pb + q * 3 + 1);
    float qz = __ldg(pb + q * 3 + 2);
    float qn = qx * qx + qy * qy + qz * qz;

    // fallback-scan query coords (thread t < QPB owns query t)
    float rqx = 0.f, rqy = 0.f, rqz = 0.f, rqn = 0.f;
    if (t < QPB) {
        int rq = (blockIdx.x * QPB + t) & 4095;
        rqx = __ldg(pb + rq * 3 + 0);
        rqy = __ldg(pb + rq * 3 + 1);
        rqz = __ldg(pb + rq * 3 + 2);
        rqn = rqx * rqx + rqy * rqy + rqz * rqz;
    }

    // preload tile 0
    {
        float x = pb[t * 3 + 0], y = pb[t * 3 + 1], z = pb[t * 3 + 2];
        sp[0][t] = make_float4(x, y, z, x * x + y * y + z * z);
    }

    // ---- Phase A: per-(query,sub) min (value only) ----
    float s0 = 3.0e38f;
    for (int tile = 0; tile < NTILE; tile++) {
        __syncthreads();   // load(tile) done; compute(tile-1) done
        if (tile + 1 < NTILE) {
            int j = (tile + 1) * TILE + t;
            float x = pb[j * 3 + 0], y = pb[j * 3 + 1], z = pb[j * 3 + 2];
            sp[(tile + 1) & 1][t] = make_float4(x, y, z, x * x + y * y + z * z);
        }
        const float4* cs = sp[tile & 1];
        int base = tile * TILE;
#pragma unroll 8
        for (int jj = 0; jj < TILE / SUBS; jj++) {
            int jl = sub + (jj << 4);
            float4 c = cs[jl];
            float dot = qx * c.x;
            dot = fmaf(qy, c.y, dot);
            dot = fmaf(qz, c.z, dot);
            float d2 = fmaf(dot, -2.0f, qn + c.w);
            bool ok = (d2 < s0) && (base + jl != q);
            s0 = ok ? d2 : s0;
        }
    }
    seedD[t] = s0;
    __syncthreads();

    if (t < QPB) {
        float mx = seedD[t * SUBS];
#pragma unroll
        for (int r = 1; r < SUBS; r++) mx = fmaxf(mx, seedD[t * SUBS + r]);
        stau[t] = mx;
    }
    // preload tile 0 for phase B (sp[0] free: phase A's last compute used sp[1])
    {
        float x = pb[t * 3 + 0], y = pb[t * 3 + 1], z = pb[t * 3 + 2];
        sp[0][t] = make_float4(x, y, z, x * x + y * y + z * z);
    }
    __syncthreads();
    float tau = stau[ql];

    // ---- Phase B: filter d2 <= tau -> buffer (d2, idx) ----
    for (int tile = 0; tile < NTILE; tile++) {
        __syncthreads();
        if (tile + 1 < NTILE) {
            int j = (tile + 1) * TILE + t;
            float x = pb[j * 3 + 0], y = pb[j * 3 + 1], z = pb[j * 3 + 2];
            sp[(tile + 1) & 1][t] = make_float4(x, y, z, x * x + y * y + z * z);
        }
        const float4* cs = sp[tile & 1];
        int base = tile * TILE;
#pragma unroll 8
        for (int jj = 0; jj < TILE / SUBS; jj++) {
            int jl = sub + (jj << 4);
            float4 c = cs[jl];
            float dot = qx * c.x;
            dot = fmaf(qy, c.y, dot);
            dot = fmaf(qz, c.z, dot);
            float d2 = fmaf(dot, -2.0f, qn + c.w);
            int jg = base + jl;
            if (d2 <= tau && jg != q) {
                int slot = atomicAdd(&scnt[ql], 1);
                if (slot < BCAP) {
                    bufD[ql][slot] = d2;
                    bufI[ql][slot] = jg;
                }
            }
        }
    }
    __syncthreads();

    // ---- Final refine: replace-max top-16 over the buffer ----
    if (t < QPB) {
        float dv[KNN];
        int   iv[KNN];
#pragma unroll
        for (int r = 0; r < KNN; r++) { dv[r] = 3.0e38f; iv[r] = 0; }
        float dmax = 3.0e38f;
        int   amax = 0;
        int n = scnt[t];
        if (n > BCAP) {
            // exact fallback: full scan with the canonical formula
            int rq = (blockIdx.x * QPB + t) & 4095;
            for (int j = 0; j < NPTS; j++) {
                if (j == rq) continue;
                float cx = pb[j * 3], cy = pb[j * 3 + 1], cz = pb[j * 3 + 2];
                float cn = cx * cx + cy * cy + cz * cz;
                float dot = rqx * cx;
                dot = fmaf(rqy, cy, dot);
                dot = fmaf(rqz, cz, dot);
                float d2 = fmaf(dot, -2.0f, rqn + cn);
                if (d2 < dmax) {
                    dv[amax] = d2; iv[amax] = j;
                    dmax = dv[0]; amax = 0;
#pragma unroll
                    for (int r = 1; r < KNN; r++)
                        if (dv[r] > dmax) { dmax = dv[r]; amax = r; }
                }
            }
        } else {
            for (int e = 0; e < n; e++) {
                float d2 = bufD[t][e];
                if (d2 < dmax) {
                    dv[amax] = d2; iv[amax] = bufI[t][e];
                    dmax = dv[0]; amax = 0;
#pragma unroll
                    for (int r = 1; r < KNN; r++)
                        if (dv[r] > dmax) { dmax = dv[r]; amax = r; }
                }
            }
        }
        int obase = (blockIdx.x * QPB + t) * KNN;
#pragma unroll
        for (int r = 0; r < KNN; r++) g_idx[obase + r] = iv[r];
    }
}

// ---------------------------------------------------------------------------
// Per-point precompute (unchanged)
// ---------------------------------------------------------------------------
__global__ __launch_bounds__(256) void pre_kernel(
    const float* __restrict__ x,
    const float* __restrict__ Wf,  const float* __restrict__ bf,
    const float* __restrict__ Wm1, const float* __restrict__ bm1,
    const float* __restrict__ Wm2, const float* __restrict__ bm2,
    const float* __restrict__ Wl,  const float* __restrict__ bl) {

    __shared__ float sw[4096];
    __shared__ float sx[64 * 68];

    int t   = threadIdx.x;
    int pt0 = blockIdx.x * 64;

    for (int i = t; i < 4096; i += 256) {
        int r = i >> 6, c = i & 63;
        sx[c * 68 + r] = __ldg(x + (pt0 + r) * 64 + c);
    }

    int m0 = (t & 15) * 4;
    int n0 = (t >> 4) * 4;

    for (int sect = 0; sect < 5; sect++) {
        __syncthreads();
        for (int i = t; i < 4096; i += 256) {
            float v;
            if      (sect == 0) v = __ldg(Wf + i)        - __ldg(Wf + 8192 + i);
            else if (sect == 1) v = __ldg(Wf + 4096 + i) + __ldg(Wf + 8192 + i);
            else if (sect == 2) v = __ldg(Wm1 + 4096 + i);
            else if (sect == 3) v = __ldg(Wm2 + 8192 + i);
            else                v = __ldg(Wl + 12288 + i);
            sw[i] = v;
        }
        __syncthreads();

        float acc[4][4];
#pragma unroll
        for (int a = 0; a < 4; a++)
#pragma unroll
            for (int bq = 0; bq < 4; bq++) acc[a][bq] = 0.0f;

#pragma unroll 4
        for (int k = 0; k < 64; k++) {
            float4 av = *(const float4*)(sx + k * 68 + m0);
            float4 wv = *(const float4*)(sw + k * 64 + n0);
            float aa[4] = {av.x, av.y, av.z, av.w};
            float ww[4] = {wv.x, wv.y, wv.z, wv.w};
#pragma unroll
            for (int mi = 0; mi < 4; mi++)
#pragma unroll
                for (int ni = 0; ni < 4; ni++)
                    acc[mi][ni] = fmaf(aa[mi], ww[ni], acc[mi][ni]);
        }

        float4 bb = make_float4(0.f, 0.f, 0.f, 0.f);
        const float* bp = (sect == 0) ? bf : (sect == 2) ? bm1
                         : (sect == 3) ? bm2 : (sect == 4) ? bl : nullptr;
        if (bp) bb = __ldg((const float4*)(bp + n0));

#pragma unroll
        for (int mi = 0; mi < 4; mi++) {
            int pt = pt0 + m0 + mi;
            float4 o = make_float4(acc[mi][0] + bb.x, acc[mi][1] + bb.y,
                                   acc[mi][2] + bb.z, acc[mi][3] + bb.w);
            float* dst;
            if (sect == 1) dst = g_Q + pt * 64 + n0;
            else {
                int off = (sect == 0) ? 0 : (sect == 2) ? 64 : (sect == 3) ? 128 : 192;
                dst = g_L + pt * 256 + off + n0;
            }
            *(float4*)dst = o;
        }
    }
}

// ---------------------------------------------------------------------------
// Weight repack (unchanged)
// ---------------------------------------------------------------------------
__global__ __launch_bounds__(256) void init_w_kernel(
    const float* __restrict__ Wm1, const float* __restrict__ Wm2,
    const float* __restrict__ Wl) {
    int e = blockIdx.x * 256 + threadIdx.x;          // 0..24575
    const float* src; int colbase;
    if (e < 4096)       { src = Wm1; colbase = 0; }
    else if (e < 12288) { src = Wm2; colbase = 64;  e -= 4096; }
    else                { src = Wl;  colbase = 192; e -= 12288; }
    int k = e >> 6, n = e & 63;
    float v = src[k * 64 + n];
    __nv_bfloat16 h = __float2bfloat16(v);
    __nv_bfloat16 l = __float2bfloat16(v - __bfloat162float(h));
    uint32_t off = (uint32_t)(n * 392 + colbase + k) * 2;
    *(__nv_bfloat16*)(g_Wpk + off)         = h;
    *(__nv_bfloat16*)(g_Wpk + 50176 + off) = l;
}

// ---------------------------------------------------------------------------
// edge_mlp (unchanged R10/R15 winner)
// ---------------------------------------------------------------------------
__device__ __forceinline__ void mma_chunk(
    uint32_t a0h, uint32_t a1h, uint32_t a2h, uint32_t a3h,
    uint32_t a0l, uint32_t a1l, uint32_t a2l, uint32_t a3l,
    uint32_t bH, uint32_t bL, float acc[8][4]) {
    uint32_t bh[4][4], bl[4][4];
#pragma unroll
    for (int pr = 0; pr < 4; pr++) {
        LDSM4(bh[pr][0], bh[pr][1], bh[pr][2], bh[pr][3], bH + pr * (16 * 784));
        LDSM4(bl[pr][0], bl[pr][1], bl[pr][2], bl[pr][3], bL + pr * (16 * 784));
    }
#pragma unroll
    for (int pr = 0; pr < 4; pr++) {
        MMA16816(acc[2 * pr],     a0h, a1h, a2h, a3h, bh[pr][0], bh[pr][1]);
        MMA16816(acc[2 * pr + 1], a0h, a1h, a2h, a3h, bh[pr][2], bh[pr][3]);
    }
#pragma unroll
    for (int pr = 0; pr < 4; pr++) {
        MMA16816(acc[2 * pr],     a0h, a1h, a2h, a3h, bl[pr][0], bl[pr][1]);
        MMA16816(acc[2 * pr + 1], a0h, a1h, a2h, a3h, bl[pr][2], bl[pr][3]);
    }
#pragma unroll
    for (int pr = 0; pr < 4; pr++) {
        MMA16816(acc[2 * pr],     a0l, a1l, a2l, a3l, bh[pr][0], bh[pr][1]);
        MMA16816(acc[2 * pr + 1], a0l, a1l, a2l, a3l, bh[pr][2], bh[pr][3]);
    }
}

__device__ __forceinline__ void epi(
    float acc[8][4], const float* __restrict__ Rbase, bool do_relu,
    uint32_t* fh, uint32_t* fl, bool store,
    float* __restrict__ outp, int lane) {
    int tg = lane >> 2, tc = lane & 3;
#pragma unroll
    for (int nt = 0; nt < 8; nt++) {
        int n0 = nt * 8 + 2 * tc;
        float2 r = __ldg((const float2*)(Rbase + n0));
        float c0 = acc[nt][0] + r.x, c1 = acc[nt][1] + r.y;
        float c2 = acc[nt][2] + r.x, c3 = acc[nt][3] + r.y;
        if (do_relu) {
            c0 = fmaxf(c0, 0.f); c1 = fmaxf(c1, 0.f);
            c2 = fmaxf(c2, 0.f); c3 = fmaxf(c3, 0.f);
        }
        if (store) {
            int s = nt >> 1, o = (nt & 1) * 2;
            hilo2(c0, c1, fh[4 * s + o],     fl[4 * s + o]);
            hilo2(c2, c3, fh[4 * s + o + 1], fl[4 * s + o + 1]);
        }
        float m0 = fmaxf(c0, c2), m1 = fmaxf(c1, c3);
        m0 = fmaxf(m0, __shfl_xor_sync(0xffffffffu, m0, 4));
        m0 = fmaxf(m0, __shfl_xor_sync(0xffffffffu, m0, 8));
        m0 = fmaxf(m0, __shfl_xor_sync(0xffffffffu, m0, 16));
        m1 = fmaxf(m1, __shfl_xor_sync(0xffffffffu, m1, 4));
        m1 = fmaxf(m1, __shfl_xor_sync(0xffffffffu, m1, 8));
        m1 = fmaxf(m1, __shfl_xor_sync(0xffffffffu, m1, 16));
        if (tg == 0) *(float2*)(outp + n0) = make_float2(m0, m1);
    }
}

__global__ __launch_bounds__(256, 1) void edge_mlp_kernel(
    const float* __restrict__ x, float* __restrict__ out) {

    extern __shared__ char sm[];
    int t = threadIdx.x, lane = t & 31, w = t >> 5;

    for (int i = t; i < 100352 / 16; i += 256)
        ((uint4*)sm)[i] = __ldg((const uint4*)g_Wpk + i);
    __syncthreads();

    uint32_t smb = smem_to_u32(sm);
    int tg = lane >> 2, tc = lane & 3;
    int n_in_pair = (lane & 7) + ((lane >> 4) & 1) * 8;
    int kh = (lane >> 3) & 1;
    uint32_t bHb = smb + n_in_pair * 784 + kh * 16;
    uint32_t bLb = bHb + WBYTES;

    for (int p = blockIdx.x * 8 + w; p < TOTPTS; p += 148 * 8) {
        int b = p >> 12;

        uint32_t f1h[16], f1l[16], f2h[16], f2l[16], f3h[16], f3l[16];

        // ---- Gather: H1 fragments direct from global + fused H1 max ----
        {
            int j0 = __ldg(g_idx + p * KNN + tg);
            int j1 = __ldg(g_idx + p * KNN + tg + 8);
            const float* P  = g_L + p * 256;
            const float* Q0 = g_Q + ((b << 12) + j0) * 64;
            const float* Q1 = g_Q + ((b << 12) + j1) * 64;
            float hm[16];
#pragma unroll
            for (int s = 0; s < 4; s++) {
                int c = 16 * s + 2 * tc;
                float2 p0 = __ldg((const float2*)(P + c));
                float2 p1 = __ldg((const float2*)(P + c + 8));
                float2 q00 = __ldg((const float2*)(Q0 + c));
                float2 q01 = __ldg((const float2*)(Q0 + c + 8));
                float2 q10 = __ldg((const float2*)(Q1 + c));
                float2 q11 = __ldg((const float2*)(Q1 + c + 8));
                float a0x = fmaxf(p0.x + q00.x, 0.f), a0y = fmaxf(p0.y + q00.y, 0.f);
                float a1x = fmaxf(p0.x + q10.x, 0.f), a1y = fmaxf(p0.y + q10.y, 0.f);
                float a2x = fmaxf(p1.x + q01.x, 0.f), a2y = fmaxf(p1.y + q01.y, 0.f);
                float a3x = fmaxf(p1.x + q11.x, 0.f), a3y = fmaxf(p1.y + q11.y, 0.f);
                hilo2(a0x, a0y, f1h[4 * s + 0], f1l[4 * s + 0]);
                hilo2(a1x, a1y, f1h[4 * s + 1], f1l[4 * s + 1]);
                hilo2(a2x, a2y, f1h[4 * s + 2], f1l[4 * s + 2]);
                hilo2(a3x, a3y, f1h[4 * s + 3], f1l[4 * s + 3]);
                hm[4 * s + 0] = fmaxf(a0x, a1x);
                hm[4 * s + 1] = fmaxf(a0y, a1y);
                hm[4 * s + 2] = fmaxf(a2x, a3x);
                hm[4 * s + 3] = fmaxf(a2y, a3y);
            }
#pragma unroll
            for (int i = 0; i < 16; i++) {
                float mv = hm[i];
                mv = fmaxf(mv, __shfl_xor_sync(0xffffffffu, mv, 4));
                mv = fmaxf(mv, __shfl_xor_sync(0xffffffffu, mv, 8));
                mv = fmaxf(mv, __shfl_xor_sync(0xffffffffu, mv, 16));
                hm[i] = mv;
            }
            if (tg == 0) {
                float* dst = out + p * 320 + 192;
#pragma unroll
                for (int s = 0; s < 4; s++) {
                    int c = 16 * s + 2 * tc;
                    *(float2*)(dst + c)     = make_float2(hm[4 * s + 0], hm[4 * s + 1]);
                    *(float2*)(dst + c + 8) = make_float2(hm[4 * s + 2], hm[4 * s + 3]);
                }
            }
            float2 xv = __ldg((const float2*)(x + p * 64 + lane * 2));
            *(float2*)(out + p * 320 + 256 + lane * 2) = xv;
        }

        float acc[8][4];

        // ---- Layer 2: H2 = relu(H1 @ Ws2 + R1); B k-cols 0..63 ----
#pragma unroll
        for (int i = 0; i < 8; i++)
#pragma unroll
            for (int q2 = 0; q2 < 4; q2++) acc[i][q2] = 0.f;
#pragma unroll
        for (int s = 0; s < 4; s++)
            mma_chunk(f1h[4*s], f1h[4*s+1], f1h[4*s+2], f1h[4*s+3],
                      f1l[4*s], f1l[4*s+1], f1l[4*s+2], f1l[4*s+3],
                      bHb + (0 + 16 * s) * 2, bLb + (0 + 16 * s) * 2, acc);
        epi(acc, g_L + p * 256 + 64, true, f2h, f2l, true,
            out + p * 320 + 128, lane);

        // ---- Layer 3: H3 = relu([H2|H1] @ Ws3 + R2); B k-cols 64..191 ----
#pragma unroll
        for (int i = 0; i < 8; i++)
#pragma unroll
            for (int q2 = 0; q2 < 4; q2++) acc[i][q2] = 0.f;
#pragma unroll
        for (int s = 0; s < 4; s++)
            mma_chunk(f2h[4*s], f2h[4*s+1], f2h[4*s+2], f2h[4*s+3],
                      f2l[4*s], f2l[4*s+1], f2l[4*s+2], f2l[4*s+3],
                      bHb + (64 + 16 * s) * 2, bLb + (64 + 16 * s) * 2, acc);
#pragma unroll
        for (int s = 4; s < 8; s++)
            mma_chunk(f1h[4*(s-4)], f1h[4*(s-4)+1], f1h[4*(s-4)+2], f1h[4*(s-4)+3],
                      f1l[4*(s-4)], f1l[4*(s-4)+1], f1l[4*(s-4)+2], f1l[4*(s-4)+3],
                      bHb + (64 + 16 * s) * 2, bLb + (64 + 16 * s) * 2, acc);
        epi(acc, g_L + p * 256 + 128, true, f3h, f3l, true,
            out + p * 320 + 64, lane);

        // ---- Layer 4: H4 = [H3|H2|H1] @ Ws4 + R3 (no relu); B k-cols 192..383 ----
#pragma unroll
        for (int i = 0; i < 8; i++)
#pragma unroll
            for (int q2 = 0; q2 < 4; q2++) acc[i][q2] = 0.f;
#pragma unroll
        for (int s = 0; s < 4; s++)
            mma_chunk(f3h[4*s], f3h[4*s+1], f3h[4*s+2], f3h[4*s+3],
                      f3l[4*s], f3l[4*s+1], f3l[4*s+2], f3l[4*s+3],
                      bHb + (192 + 16 * s) * 2, bLb + (192 + 16 * s) * 2, acc);
#pragma unroll
        for (int s = 4; s < 8; s++)
            mma_chunk(f2h[4*(s-4)], f2h[4*(s-4)+1], f2h[4*(s-4)+2], f2h[4*(s-4)+3],
                      f2l[4*(s-4)], f2l[4*(s-4)+1], f2l[4*(s-4)+2], f2l[4*(s-4)+3],
                      bHb + (192 + 16 * s) * 2, bLb + (192 + 16 * s) * 2, acc);
#pragma unroll
        for (int s = 8; s < 12; s++)
            mma_chunk(f1h[4*(s-8)], f1h[4*(s-8)+1], f1h[4*(s-8)+2], f1h[4*(s-8)+3],
                      f1l[4*(s-8)], f1l[4*(s-8)+1], f1l[4*(s-8)+2], f1l[4*(s-8)+3],
                      bHb + (192 + 16 * s) * 2, bLb + (192 + 16 * s) * 2, acc);
        epi(acc, g_L + p * 256 + 192, false, f2h, f2l, false,
            out + p * 320, lane);
    }
}

// ---------------------------------------------------------------------------
extern "C" void kernel_launch(void* const* d_in, const int* in_sizes, int n_in,
                              void* d_out, int out_size) {
    const float* x   = (const float*)d_in[0];
    const float* pos = (const float*)d_in[1];
    const float* Wf  = (const float*)d_in[2];
    const float* bf  = (const float*)d_in[3];
    const float* Wm1 = (const float*)d_in[4];
    const float* bm1 = (const float*)d_in[5];
    const float* Wm2 = (const float*)d_in[6];
    const float* bm2 = (const float*)d_in[7];
    const float* Wl  = (const float*)d_in[8];
    const float* bl  = (const float*)d_in[9];
    float* out = (float*)d_out;

    cudaFuncSetAttribute(edge_mlp_kernel,
                         cudaFuncAttributeMaxDynamicSharedMemorySize,
                         MAIN_SMEM_BYTES);

    init_w_kernel<<<96, 256>>>(Wm1, Wm2, Wl);
    knn_kernel<<<TOTPTS / QPB, 256>>>(pos);
    pre_kernel<<<256, 256>>>(x, Wf, bf, Wm1, bm1, Wm2, bm2, Wl, bl);
    edge_mlp_kernel<<<148, 256, MAIN_SMEM_BYTES>>>(x, out);
}

// round 17
// speedup vs baseline: 2.4606x; 2.4606x over previous
#include <cuda_runtime.h>
#include <cuda_bf16.h>
#include <cstdint>

#define TOTPTS 16384
#define NPTS   4096
#define KNN    16

// ---- knn v9 config: R15 algorithm, TILE doubled to halve barrier count ----
#define QPB  16
#define SUBS 16
#define TILE 512
#define PRE_N 1024               // candidates scanned in phase A (valid-subset tau)
#define KNN_SMEM_BYTES (TILE * 16 + QPB * TILE * 4 + QPB * KNN * 4 * 2 + QPB * 8)

// ---- edge_mlp smem: weights only ----
#define WBYTES  50176            // 64*392*2
#define MAIN_SMEM_BYTES 100352   // hi + lo

// Scratch (allocation-free rule: device globals)
__device__ __align__(16) float g_L[TOTPTS * 256];   // [P | R1 | R2 | R3] per point
__device__ __align__(16) float g_Q[TOTPTS * 64];    // Q per point
__device__ int g_idx[TOTPTS * KNN];
__device__ __align__(16) unsigned char g_Wpk[100352]; // packed bf16 hi(50176)+lo(50176)

// ===================== helpers =====================
__device__ __forceinline__ uint32_t smem_to_u32(const void* p) {
    uint32_t a;
    asm("{ .reg .u64 t; cvta.to.shared.u64 t, %1; cvt.u32.u64 %0, t; }" : "=r"(a) : "l"(p));
    return a;
}
#define LDSM4(r0, r1, r2, r3, addr) \
    asm volatile("ldmatrix.sync.aligned.m8n8.x4.shared.b16 {%0,%1,%2,%3}, [%4];" \
        : "=r"(r0), "=r"(r1), "=r"(r2), "=r"(r3) : "r"(addr))
#define MMA16816(c, a0, a1, a2, a3, b0, b1) \
    asm volatile("mma.sync.aligned.m16n8k16.row.col.f32.bf16.bf16.f32 " \
        "{%0,%1,%2,%3}, {%4,%5,%6,%7}, {%8,%9}, {%0,%1,%2,%3};" \
        : "+f"((c)[0]), "+f"((c)[1]), "+f"((c)[2]), "+f"((c)[3]) \
        : "r"(a0), "r"(a1), "r"(a2), "r"(a3), "r"(b0), "r"(b1))

__device__ __forceinline__ void hilo2(float a, float b, uint32_t& h, uint32_t& l) {
    __nv_bfloat16 ha = __float2bfloat16(a), hb = __float2bfloat16(b);
    float ra = a - __bfloat162float(ha), rb = b - __bfloat162float(hb);
    __nv_bfloat162 H; H.x = ha; H.y = hb;
    __nv_bfloat162 L; L.x = __float2bfloat16(ra); L.y = __float2bfloat16(rb);
    h = *(uint32_t*)&H; l = *(uint32_t*)&L;
}

// ---------------------------------------------------------------------------
// KNN v9 == v7 (R15 passing winner) with TILE=512:
//  - Phase A: per-(query,sub) top-1 over first PRE_N candidates; tau0 = max
//    of 16 distinct sub-minima >= d16 (provable subset bound).
//  - Phase B: tau-filter (tau tightens every tile via per-tile exact refine
//    with dedup vs seeds) -> the filter stays cheap and there is NO
//    fallback path. Buffer stores local index; refine recomputes d2 from
//    the resident tile with the canonical fmaf chain -> selection identical
//    to every passing round.
//  - Per tile at most TILE candidates can pass (scnt reset per tile), so
//    slot < TILE by construction.
// ---------------------------------------------------------------------------
__global__ __launch_bounds__(256) void knn_kernel(const float* __restrict__ pos) {
    extern __shared__ char kshm[];
    float4* sp    = (float4*)kshm;                                     // 8 KB
    int*    bufI  = (int*)(kshm + TILE * 16);                          // 32 KB
    float*  seedD = (float*)(kshm + TILE * 16 + QPB * TILE * 4);
    int*    seedI = (int*)(kshm + TILE * 16 + QPB * TILE * 4 + QPB * KNN * 4);
    int*    scnt  = (int*)(kshm + TILE * 16 + QPB * TILE * 4 + QPB * KNN * 8);
    float*  stau  = (float*)(kshm + TILE * 16 + QPB * TILE * 4 + QPB * KNN * 8 + QPB * 4);

    int t   = threadIdx.x;
    int ql  = t >> 4;                      // 0..15 query within block
    int sub = t & 15;
    int qg  = blockIdx.x * QPB + ql;
    int b   = qg >> 12;
    int q   = qg & 4095;
    const float* pb = pos + b * NPTS * 3;

    if (t < QPB) scnt[t] = 0;

    float qx = __ldg(pb + q * 3 + 0);
    float qy = __ldg(pb + q * 3 + 1);
    float qz = __ldg(pb + q * 3 + 2);
    float qn = qx * qx + qy * qy + qz * qz;

    float rqx = 0.f, rqy = 0.f, rqz = 0.f, rqn = 0.f;
    if (t < QPB) {
        int rq = (blockIdx.x * QPB + t) & 4095;
        rqx = __ldg(pb + rq * 3 + 0);
        rqy = __ldg(pb + rq * 3 + 1);
        rqz = __ldg(pb + rq * 3 + 2);
        rqn = rqx * rqx + rqy * rqy + rqz * rqz;
    }

    // ---- Phase A: per-(query,sub) top-1 over first PRE_N candidates ----
    float s0 = 3.0e38f;
    int   i0 = 0;

    for (int t0 = 0; t0 < PRE_N; t0 += TILE) {
        __syncthreads();
        for (int i = t; i < TILE; i += 256) {
            int j = t0 + i;
            float x = pb[j * 3 + 0], y = pb[j * 3 + 1], z = pb[j * 3 + 2];
            sp[i] = make_float4(x, y, z, x * x + y * y + z * z);
        }
        __syncthreads();
#pragma unroll 8
        for (int jj = 0; jj < TILE / SUBS; jj++) {
            int jl = sub + (jj << 4);
            float4 c = sp[jl];
            float dot = qx * c.x;
            dot = fmaf(qy, c.y, dot);
            dot = fmaf(qz, c.z, dot);
            float d2 = fmaf(dot, -2.0f, qn + c.w);
            int jg = t0 + jl;
            if (d2 < s0 && jg != q) { s0 = d2; i0 = jg; }
        }
    }
    seedD[ql * KNN + sub] = s0;
    seedI[ql * KNN + sub] = i0;
    __syncthreads();

    // ---- Seed refine state: 16 distinct sub-minima; tau0 = their max ----
    float dv[KNN];
    int   iv[KNN];
    float dmax = 0.f;
    int   amax = 0;
    if (t < QPB) {
#pragma unroll
        for (int r = 0; r < KNN; r++) {
            dv[r] = seedD[t * KNN + r];
            iv[r] = seedI[t * KNN + r];
        }
        dmax = dv[0]; amax = 0;
#pragma unroll
        for (int r = 1; r < KNN; r++)
            if (dv[r] > dmax) { dmax = dv[r]; amax = r; }
        stau[t] = dmax;
    }

    // ---- Phase B: tau-filter + per-tile refine (exact, dedup vs seeds) ----
    for (int t0 = 0; t0 < NPTS; t0 += TILE) {
        __syncthreads();
        for (int i = t; i < TILE; i += 256) {
            int j = t0 + i;
            float x = pb[j * 3 + 0], y = pb[j * 3 + 1], z = pb[j * 3 + 2];
            sp[i] = make_float4(x, y, z, x * x + y * y + z * z);
        }
        __syncthreads();

        float tau = stau[ql];
        int*  bI  = bufI + ql * TILE;

#pragma unroll 8
        for (int jj = 0; jj < TILE / SUBS; jj++) {
            int jl = sub + (jj << 4);
            float4 c = sp[jl];
            float dot = qx * c.x;
            dot = fmaf(qy, c.y, dot);
            dot = fmaf(qz, c.z, dot);
            float d2 = fmaf(dot, -2.0f, qn + c.w);
            int jg = t0 + jl;
            if (d2 < tau && jg != q) {
                int slot = atomicAdd(&scnt[ql], 1);
                if (slot >= TILE) slot = TILE - 1;   // unreachable; defensive
                bI[slot] = jl;
            }
        }
        __syncthreads();

        if (t < QPB) {
            int n = scnt[t];
            if (n > TILE) n = TILE;
            const int* rI = bufI + t * TILE;
            for (int e = 0; e < n; e++) {
                int jl = rI[e];
                float4 c = sp[jl];
                float dot = rqx * c.x;
                dot = fmaf(rqy, c.y, dot);
                dot = fmaf(rqz, c.z, dot);
                float d2 = fmaf(dot, -2.0f, rqn + c.w);
                if (d2 < dmax) {
                    int jg = t0 + jl;
                    bool dup = false;
#pragma unroll
                    for (int r = 0; r < KNN; r++) dup = dup || (iv[r] == jg);
                    if (!dup) {
                        dv[amax] = d2; iv[amax] = jg;
                        dmax = dv[0]; amax = 0;
#pragma unroll
                        for (int r = 1; r < KNN; r++)
                            if (dv[r] > dmax) { dmax = dv[r]; amax = r; }
                    }
                }
            }
            scnt[t] = 0;
            stau[t] = dmax;
        }
    }

    if (t < QPB) {
        int obase = (blockIdx.x * QPB + t) * KNN;
#pragma unroll
        for (int r = 0; r < KNN; r++) g_idx[obase + r] = iv[r];
    }
}

// ---------------------------------------------------------------------------
// Per-point precompute (unchanged)
// ---------------------------------------------------------------------------
__global__ __launch_bounds__(256) void pre_kernel(
    const float* __restrict__ x,
    const float* __restrict__ Wf,  const float* __restrict__ bf,
    const float* __restrict__ Wm1, const float* __restrict__ bm1,
    const float* __restrict__ Wm2, const float* __restrict__ bm2,
    const float* __restrict__ Wl,  const float* __restrict__ bl) {

    __shared__ float sw[4096];
    __shared__ float sx[64 * 68];

    int t   = threadIdx.x;
    int pt0 = blockIdx.x * 64;

    for (int i = t; i < 4096; i += 256) {
        int r = i >> 6, c = i & 63;
        sx[c * 68 + r] = __ldg(x + (pt0 + r) * 64 + c);
    }

    int m0 = (t & 15) * 4;
    int n0 = (t >> 4) * 4;

    for (int sect = 0; sect < 5; sect++) {
        __syncthreads();
        for (int i = t; i < 4096; i += 256) {
            float v;
            if      (sect == 0) v = __ldg(Wf + i)        - __ldg(Wf + 8192 + i);
            else if (sect == 1) v = __ldg(Wf + 4096 + i) + __ldg(Wf + 8192 + i);
            else if (sect == 2) v = __ldg(Wm1 + 4096 + i);
            else if (sect == 3) v = __ldg(Wm2 + 8192 + i);
            else                v = __ldg(Wl + 12288 + i);
            sw[i] = v;
        }
        __syncthreads();

        float acc[4][4];
#pragma unroll
        for (int a = 0; a < 4; a++)
#pragma unroll
            for (int bq = 0; bq < 4; bq++) acc[a][bq] = 0.0f;

#pragma unroll 4
        for (int k = 0; k < 64; k++) {
            float4 av = *(const float4*)(sx + k * 68 + m0);
            float4 wv = *(const float4*)(sw + k * 64 + n0);
            float aa[4] = {av.x, av.y, av.z, av.w};
            float ww[4] = {wv.x, wv.y, wv.z, wv.w};
#pragma unroll
            for (int mi = 0; mi < 4; mi++)
#pragma unroll
                for (int ni = 0; ni < 4; ni++)
                    acc[mi][ni] = fmaf(aa[mi], ww[ni], acc[mi][ni]);
        }

        float4 bb = make_float4(0.f, 0.f, 0.f, 0.f);
        const float* bp = (sect == 0) ? bf : (sect == 2) ? bm1
                         : (sect == 3) ? bm2 : (sect == 4) ? bl : nullptr;
        if (bp) bb = __ldg((const float4*)(bp + n0));

#pragma unroll
        for (int mi = 0; mi < 4; mi++) {
            int pt = pt0 + m0 + mi;
            float4 o = make_float4(acc[mi][0] + bb.x, acc[mi][1] + bb.y,
                                   acc[mi][2] + bb.z, acc[mi][3] + bb.w);
            float* dst;
            if (sect == 1) dst = g_Q + pt * 64 + n0;
            else {
                int off = (sect == 0) ? 0 : (sect == 2) ? 64 : (sect == 3) ? 128 : 192;
                dst = g_L + pt * 256 + off + n0;
            }
            *(float4*)dst = o;
        }
    }
}

// ---------------------------------------------------------------------------
// Weight repack (unchanged)
// ---------------------------------------------------------------------------
__global__ __launch_bounds__(256) void init_w_kernel(
    const float* __restrict__ Wm1, const float* __restrict__ Wm2,
    const float* __restrict__ Wl) {
    int e = blockIdx.x * 256 + threadIdx.x;          // 0..24575
    const float* src; int colbase;
    if (e < 4096)       { src = Wm1; colbase = 0; }
    else if (e < 12288) { src = Wm2; colbase = 64;  e -= 4096; }
    else                { src = Wl;  colbase = 192; e -= 12288; }
    int k = e >> 6, n = e & 63;
    float v = src[k * 64 + n];
    __nv_bfloat16 h = __float2bfloat16(v);
    __nv_bfloat16 l = __float2bfloat16(v - __bfloat162float(h));
    uint32_t off = (uint32_t)(n * 392 + colbase + k) * 2;
    *(__nv_bfloat16*)(g_Wpk + off)         = h;
    *(__nv_bfloat16*)(g_Wpk + 50176 + off) = l;
}

// ---------------------------------------------------------------------------
// edge_mlp (unchanged R10/R15 winner)
// ---------------------------------------------------------------------------
__device__ __forceinline__ void mma_chunk(
    uint32_t a0h, uint32_t a1h, uint32_t a2h, uint32_t a3h,
    uint32_t a0l, uint32_t a1l, uint32_t a2l, uint32_t a3l,
    uint32_t bH, uint32_t bL, float acc[8][4]) {
    uint32_t bh[4][4], bl[4][4];
#pragma unroll
    for (int pr = 0; pr < 4; pr++) {
        LDSM4(bh[pr][0], bh[pr][1], bh[pr][2], bh[pr][3], bH + pr * (16 * 784));
        LDSM4(bl[pr][0], bl[pr][1], bl[pr][2], bl[pr][3], bL + pr * (16 * 784));
    }
#pragma unroll
    for (int pr = 0; pr < 4; pr++) {
        MMA16816(acc[2 * pr],     a0h, a1h, a2h, a3h, bh[pr][0], bh[pr][1]);
        MMA16816(acc[2 * pr + 1], a0h, a1h, a2h, a3h, bh[pr][2], bh[pr][3]);
    }
#pragma unroll
    for (int pr = 0; pr < 4; pr++) {
        MMA16816(acc[2 * pr],     a0h, a1h, a2h, a3h, bl[pr][0], bl[pr][1]);
        MMA16816(acc[2 * pr + 1], a0h, a1h, a2h, a3h, bl[pr][2], bl[pr][3]);
    }
#pragma unroll
    for (int pr = 0; pr < 4; pr++) {
        MMA16816(acc[2 * pr],     a0l, a1l, a2l, a3l, bh[pr][0], bh[pr][1]);
        MMA16816(acc[2 * pr + 1], a0l, a1l, a2l, a3l, bh[pr][2], bh[pr][3]);
    }
}

__device__ __forceinline__ void epi(
    float acc[8][4], const float* __restrict__ Rbase, bool do_relu,
    uint32_t* fh, uint32_t* fl, bool store,
    float* __restrict__ outp, int lane) {
    int tg = lane >> 2, tc = lane & 3;
#pragma unroll
    for (int nt = 0; nt < 8; nt++) {
        int n0 = nt * 8 + 2 * tc;
        float2 r = __ldg((const float2*)(Rbase + n0));
        float c0 = acc[nt][0] + r.x, c1 = acc[nt][1] + r.y;
        float c2 = acc[nt][2] + r.x, c3 = acc[nt][3] + r.y;
        if (do_relu) {
            c0 = fmaxf(c0, 0.f); c1 = fmaxf(c1, 0.f);
            c2 = fmaxf(c2, 0.f); c3 = fmaxf(c3, 0.f);
        }
        if (store) {
            int s = nt >> 1, o = (nt & 1) * 2;
            hilo2(c0, c1, fh[4 * s + o],     fl[4 * s + o]);
            hilo2(c2, c3, fh[4 * s + o + 1], fl[4 * s + o + 1]);
        }
        float m0 = fmaxf(c0, c2), m1 = fmaxf(c1, c3);
        m0 = fmaxf(m0, __shfl_xor_sync(0xffffffffu, m0, 4));
        m0 = fmaxf(m0, __shfl_xor_sync(0xffffffffu, m0, 8));
        m0 = fmaxf(m0, __shfl_xor_sync(0xffffffffu, m0, 16));
        m1 = fmaxf(m1, __shfl_xor_sync(0xffffffffu, m1, 4));
        m1 = fmaxf(m1, __shfl_xor_sync(0xffffffffu, m1, 8));
        m1 = fmaxf(m1, __shfl_xor_sync(0xffffffffu, m1, 16));
        if (tg == 0) *(float2*)(outp + n0) = make_float2(m0, m1);
    }
}

__global__ __launch_bounds__(256, 1) void edge_mlp_kernel(
    const float* __restrict__ x, float* __restrict__ out) {

    extern __shared__ char sm[];
    int t = threadIdx.x, lane = t & 31, w = t >> 5;

    for (int i = t; i < 100352 / 16; i += 256)
        ((uint4*)sm)[i] = __ldg((const uint4*)g_Wpk + i);
    __syncthreads();

    uint32_t smb = smem_to_u32(sm);
    int tg = lane >> 2, tc = lane & 3;
    int n_in_pair = (lane & 7) + ((lane >> 4) & 1) * 8;
    int kh = (lane >> 3) & 1;
    uint32_t bHb = smb + n_in_pair * 784 + kh * 16;
    uint32_t bLb = bHb + WBYTES;

    for (int p = blockIdx.x * 8 + w; p < TOTPTS; p += 148 * 8) {
        int b = p >> 12;

        uint32_t f1h[16], f1l[16], f2h[16], f2l[16], f3h[16], f3l[16];

        // ---- Gather: H1 fragments direct from global + fused H1 max ----
        {
            int j0 = __ldg(g_idx + p * KNN + tg);
            int j1 = __ldg(g_idx + p * KNN + tg + 8);
            const float* P  = g_L + p * 256;
            const float* Q0 = g_Q + ((b << 12) + j0) * 64;
            const float* Q1 = g_Q + ((b << 12) + j1) * 64;
            float hm[16];
#pragma unroll
            for (int s = 0; s < 4; s++) {
                int c = 16 * s + 2 * tc;
                float2 p0 = __ldg((const float2*)(P + c));
                float2 p1 = __ldg((const float2*)(P + c + 8));
                float2 q00 = __ldg((const float2*)(Q0 + c));
                float2 q01 = __ldg((const float2*)(Q0 + c + 8));
                float2 q10 = __ldg((const float2*)(Q1 + c));
                float2 q11 = __ldg((const float2*)(Q1 + c + 8));
                float a0x = fmaxf(p0.x + q00.x, 0.f), a0y = fmaxf(p0.y + q00.y, 0.f);
                float a1x = fmaxf(p0.x + q10.x, 0.f), a1y = fmaxf(p0.y + q10.y, 0.f);
                float a2x = fmaxf(p1.x + q01.x, 0.f), a2y = fmaxf(p1.y + q01.y, 0.f);
                float a3x = fmaxf(p1.x + q11.x, 0.f), a3y = fmaxf(p1.y + q11.y, 0.f);
                hilo2(a0x, a0y, f1h[4 * s + 0], f1l[4 * s + 0]);
                hilo2(a1x, a1y, f1h[4 * s + 1], f1l[4 * s + 1]);
                hilo2(a2x, a2y, f1h[4 * s + 2], f1l[4 * s + 2]);
                hilo2(a3x, a3y, f1h[4 * s + 3], f1l[4 * s + 3]);
                hm[4 * s + 0] = fmaxf(a0x, a1x);
                hm[4 * s + 1] = fmaxf(a0y, a1y);
                hm[4 * s + 2] = fmaxf(a2x, a3x);
                hm[4 * s + 3] = fmaxf(a2y, a3y);
            }
#pragma unroll
            for (int i = 0; i < 16; i++) {
                float mv = hm[i];
                mv = fmaxf(mv, __shfl_xor_sync(0xffffffffu, mv, 4));
                mv = fmaxf(mv, __shfl_xor_sync(0xffffffffu, mv, 8));
                mv = fmaxf(mv, __shfl_xor_sync(0xffffffffu, mv, 16));
                hm[i] = mv;
            }
            if (tg == 0) {
                float* dst = out + p * 320 + 192;
#pragma unroll
                for (int s = 0; s < 4; s++) {
                    int c = 16 * s + 2 * tc;
                    *(float2*)(dst + c)     = make_float2(hm[4 * s + 0], hm[4 * s + 1]);
                    *(float2*)(dst + c + 8) = make_float2(hm[4 * s + 2], hm[4 * s + 3]);
                }
            }
            float2 xv = __ldg((const float2*)(x + p * 64 + lane * 2));
            *(float2*)(out + p * 320 + 256 + lane * 2) = xv;
        }

        float acc[8][4];

        // ---- Layer 2: H2 = relu(H1 @ Ws2 + R1); B k-cols 0..63 ----
#pragma unroll
        for (int i = 0; i < 8; i++)
#pragma unroll
            for (int q2 = 0; q2 < 4; q2++) acc[i][q2] = 0.f;
#pragma unroll
        for (int s = 0; s < 4; s++)
            mma_chunk(f1h[4*s], f1h[4*s+1], f1h[4*s+2], f1h[4*s+3],
                      f1l[4*s], f1l[4*s+1], f1l[4*s+2], f1l[4*s+3],
                      bHb + (0 + 16 * s) * 2, bLb + (0 + 16 * s) * 2, acc);
        epi(acc, g_L + p * 256 + 64, true, f2h, f2l, true,
            out + p * 320 + 128, lane);

        // ---- Layer 3: H3 = relu([H2|H1] @ Ws3 + R2); B k-cols 64..191 ----
#pragma unroll
        for (int i = 0; i < 8; i++)
#pragma unroll
            for (int q2 = 0; q2 < 4; q2++) acc[i][q2] = 0.f;
#pragma unroll
        for (int s = 0; s < 4; s++)
            mma_chunk(f2h[4*s], f2h[4*s+1], f2h[4*s+2], f2h[4*s+3],
                      f2l[4*s], f2l[4*s+1], f2l[4*s+2], f2l[4*s+3],
                      bHb + (64 + 16 * s) * 2, bLb + (64 + 16 * s) * 2, acc);
#pragma unroll
        for (int s = 4; s < 8; s++)
            mma_chunk(f1h[4*(s-4)], f1h[4*(s-4)+1], f1h[4*(s-4)+2], f1h[4*(s-4)+3],
                      f1l[4*(s-4)], f1l[4*(s-4)+1], f1l[4*(s-4)+2], f1l[4*(s-4)+3],
                      bHb + (64 + 16 * s) * 2, bLb + (64 + 16 * s) * 2, acc);
        epi(acc, g_L + p * 256 + 128, true, f3h, f3l, true,
            out + p * 320 + 64, lane);

        // ---- Layer 4: H4 = [H3|H2|H1] @ Ws4 + R3 (no relu); B k-cols 192..383 ----
#pragma unroll
        for (int i = 0; i < 8; i++)
#pragma unroll
            for (int q2 = 0; q2 < 4; q2++) acc[i][q2] = 0.f;
#pragma unroll
        for (int s = 0; s < 4; s++)
            mma_chunk(f3h[4*s], f3h[4*s+1], f3h[4*s+2], f3h[4*s+3],
                      f3l[4*s], f3l[4*s+1], f3l[4*s+2], f3l[4*s+3],
                      bHb + (192 + 16 * s) * 2, bLb + (192 + 16 * s) * 2, acc);
#pragma unroll
        for (int s = 4; s < 8; s++)
            mma_chunk(f2h[4*(s-4)], f2h[4*(s-4)+1], f2h[4*(s-4)+2], f2h[4*(s-4)+3],
                      f2l[4*(s-4)], f2l[4*(s-4)+1], f2l[4*(s-4)+2], f2l[4*(s-4)+3],
                      bHb + (192 + 16 * s) * 2, bLb + (192 + 16 * s) * 2, acc);
#pragma unroll
        for (int s = 8; s < 12; s++)
            mma_chunk(f1h[4*(s-8)], f1h[4*(s-8)+1], f1h[4*(s-8)+2], f1h[4*(s-8)+3],
                      f1l[4*(s-8)], f1l[4*(s-8)+1], f1l[4*(s-8)+2], f1l[4*(s-8)+3],
                      bHb + (192 + 16 * s) * 2, bLb + (192 + 16 * s) * 2, acc);
        epi(acc, g_L + p * 256 + 192, false, f2h, f2l, false,
            out + p * 320, lane);
    }
}

// ---------------------------------------------------------------------------
extern "C" void kernel_launch(void* const* d_in, const int* in_sizes, int n_in,
                              void* d_out, int out_size) {
    const float* x   = (const float*)d_in[0];
    const float* pos = (const float*)d_in[1];
    const float* Wf  = (const float*)d_in[2];
    const float* bf  = (const float*)d_in[3];
    const float* Wm1 = (const float*)d_in[4];
    const float* bm1 = (const float*)d_in[5];
    const float* Wm2 = (const float*)d_in[6];
    const float* bm2 = (const float*)d_in[7];
    const float* Wl  = (const float*)d_in[8];
    const float* bl  = (const float*)d_in[9];
    float* out = (float*)d_out;

    cudaFuncSetAttribute(knn_kernel,
                         cudaFuncAttributeMaxDynamicSharedMemorySize,
                         KNN_SMEM_BYTES);
    cudaFuncSetAttribute(edge_mlp_kernel,
                         cudaFuncAttributeMaxDynamicSharedMemorySize,
                         MAIN_SMEM_BYTES);

    init_w_kernel<<<96, 256>>>(Wm1, Wm2, Wl);
    knn_kernel<<<TOTPTS / QPB, 256, KNN_SMEM_BYTES>>>(pos);
    pre_kernel<<<256, 256>>>(x, Wf, bf, Wm1, bm1, Wm2, bm2, Wl, bl);
    edge_mlp_kernel<<<148, 256, MAIN_SMEM_BYTES>>>(x, out);
}